// round 9
// baseline (speedup 1.0000x reference)
#include <cuda_runtime.h>

#define B_CHAIN 16384
#define S_SIDE 15
#define NATM (1 + B_CHAIN + B_CHAIN * S_SIDE)

#define NBB 32            // backbone blocks
#define TPB 512           // threads per block (NBB*TPB == B_CHAIN)
#define NWARP (TPB / 32)  // 16
#define CPS 64            // chains per side block
#define NSIDE (B_CHAIN / CPS)   // 256
#define NGRID (NBB + NSIDE)     // 288

// Scratch (device globals, zero-initialized at load; reset by the last block
// each run via g_done so every graph replay starts clean).
__device__ float g_global[12 * B_CHAIN];   // backbone global transforms (SoA)
__device__ float g_agg[NBB * 12];          // block aggregates (AoS)
__device__ int   g_flag[NBB];              // lookback publish flags
__device__ int   g_ready[NBB];             // g_global chunk-ready flags
__device__ int   g_done;                   // completion counter

struct Aff { float m[12]; };  // row-major 3x4 affine; m[r*4+3] = translation

__device__ __forceinline__ Aff aff_identity() {
    Aff I;
#pragma unroll
    for (int k = 0; k < 12; ++k) I.m[k] = 0.0f;
    I.m[0] = I.m[5] = I.m[10] = 1.0f;
    return I;
}

__device__ __forceinline__ Aff aff_mul(const Aff& A, const Aff& B) {
    Aff C;
#pragma unroll
    for (int r = 0; r < 3; ++r) {
#pragma unroll
        for (int c = 0; c < 4; ++c) {
            float s = A.m[r*4+0] * B.m[0*4+c]
                    + A.m[r*4+1] * B.m[1*4+c]
                    + A.m[r*4+2] * B.m[2*4+c];
            if (c == 3) s += A.m[r*4+3];
            C.m[r*4+c] = s;
        }
    }
    return C;
}

__device__ __forceinline__ Aff shfl_up_aff(const Aff& a, int delta, int width) {
    Aff r;
#pragma unroll
    for (int k = 0; k < 12; ++k)
        r.m[k] = __shfl_up_sync(0xffffffffu, a.m[k], delta, width);
    return r;
}

__device__ __forceinline__ Aff shfl_down_aff(const Aff& a, int delta) {
    Aff r;
#pragma unroll
    for (int k = 0; k < 12; ++k)
        r.m[k] = __shfl_down_sync(0xffffffffu, a.m[k], delta, 32);
    return r;
}

// Per-node transform, closed forms. ALWAYS precise sincosf: it is FMA-pipe
// polynomial (no MUFU). __sincosf would put 6 MUFU ops per node on a pipe
// with rt=8/SMSP -> 1.47M MUFU ops = ~10us chip floor. FMA floor is ~2us.
// doftype==2 (bond): Rx(d0) Rz(d1) T(d2,0,0) Rx(d3)
// doftype==1 (jump): T(d0,d1,d2) Rz(d5) Ry(d4) Rx(d3)
// doftype==0: identity
__device__ __forceinline__ Aff build_ht_from(int dt, float4 d, int n,
                                             const float* __restrict__ full_dofs) {
    if (dt == 0) return aff_identity();
    Aff H;
    if (dt == 2) {
        float sa, ca, sb, cb, sc, cc;
        sincosf(d.x, &sa, &ca);
        sincosf(d.y, &sb, &cb);
        sincosf(d.w, &sc, &cc);
        float x = d.z;
        H.m[0] = cb;      H.m[1]  = -sb * cc;             H.m[2]  = sb * sc;               H.m[3]  = cb * x;
        H.m[4] = ca * sb; H.m[5]  = ca * cb * cc - sa*sc; H.m[6]  = -ca * cb * sc - sa*cc; H.m[7]  = ca * sb * x;
        H.m[8] = sa * sb; H.m[9]  = sa * cb * cc + ca*sc; H.m[10] = -sa * cb * sc + ca*cc; H.m[11] = sa * sb * x;
    } else {
        float a = d.w;
        float b = full_dofs[n * 9 + 4];
        float g = full_dofs[n * 9 + 5];
        float sa, ca, sb, cb, sg, cg;
        sincosf(a, &sa, &ca);
        sincosf(b, &sb, &cb);
        sincosf(g, &sg, &cg);
        H.m[0] = cg * cb; H.m[1]  = cg * sb * sa - sg * ca; H.m[2]  = cg * sb * ca + sg * sa; H.m[3]  = d.x;
        H.m[4] = sg * cb; H.m[5]  = sg * sb * sa + cg * ca; H.m[6]  = sg * sb * ca - cg * sa; H.m[7]  = d.y;
        H.m[8] = -sb;     H.m[9]  = cb * sa;                H.m[10] = cb * ca;                H.m[11] = d.z;
    }
    return H;
}

// ---------------- one kernel, role-split grid --------------------------------
__global__ void __launch_bounds__(TPB, 2)
k_all(const float4* __restrict__ dofs4,
      const float* __restrict__ full_dofs,
      const int* __restrict__ doftype,
      const int* __restrict__ kin_id,
      float* __restrict__ out) {
    const int bid = blockIdx.x;
    const int t   = threadIdx.x;

    if (bid < NBB) {
        // ================= BACKBONE =================
        const int item = bid * TPB + t;
        const int n    = item + 1;
        const int lane = t & 31;
        const int warp = t >> 5;

        __shared__ float s_agg[NWARP][12];  // per-warp aggregates
        __shared__ float s_inc[NWARP][12];  // inclusive scan of aggregates
        __shared__ float s_exc[12];         // exclusive block prefix

        Aff M = build_ht_from(doftype[n], dofs4[n - 1], n, full_dofs);

        // warp shuffle inclusive scan
#pragma unroll
        for (int d = 1; d < 32; d <<= 1) {
            Aff P = shfl_up_aff(M, d, 32);
            if (lane >= d) M = aff_mul(P, M);
        }
        if (lane == 31) {
#pragma unroll
            for (int k = 0; k < 12; ++k) s_agg[warp][k] = M.m[k];
        }
        __syncthreads();

        if (warp == 0) {
            // scan the 16 warp aggregates (lanes 0..15)
            Aff A = aff_identity();
            if (lane < NWARP) {
#pragma unroll
                for (int k = 0; k < 12; ++k) A.m[k] = s_agg[lane][k];
            }
#pragma unroll
            for (int d = 1; d < NWARP; d <<= 1) {
                Aff P = shfl_up_aff(A, d, NWARP);
                if (lane >= d && lane < NWARP) A = aff_mul(P, A);
            }
            if (lane < NWARP) {
#pragma unroll
                for (int k = 0; k < 12; ++k) s_inc[lane][k] = A.m[k];
            }
            // publish block aggregate ASAP (lane 15 holds it)
            if (lane == NWARP - 1) {
#pragma unroll
                for (int k = 0; k < 12; ++k) g_agg[bid * 12 + k] = A.m[k];
                __threadfence();
                atomicExch(&g_flag[bid], 1);
            }
            // lookback: lane i covers predecessor block i
            Aff V = aff_identity();
            if (lane < bid) {
                volatile int* vf = (volatile int*)g_flag;
                while (vf[lane] == 0) { __nanosleep(32); }
                __threadfence();
#pragma unroll
                for (int k = 0; k < 12; ++k) V.m[k] = __ldcg(&g_agg[lane * 12 + k]);
            }
            __syncwarp();
            // ordered tree reduce over 32 lanes (low index = left operand)
#pragma unroll
            for (int d = 1; d < 32; d <<= 1) {
                Aff H = shfl_down_aff(V, d);
                if ((lane & (2 * d - 1)) == 0) V = aff_mul(V, H);
            }
            if (lane == 0) {
#pragma unroll
                for (int k = 0; k < 12; ++k) s_exc[k] = V.m[k];
            }
        }
        __syncthreads();

        // fixup: M_global = E * (W_warp * M)
        if (warp > 0) {
            Aff W;
#pragma unroll
            for (int k = 0; k < 12; ++k) W.m[k] = s_inc[warp - 1][k];
            M = aff_mul(W, M);
        }
        {
            Aff E;
#pragma unroll
            for (int k = 0; k < 12; ++k) E.m[k] = s_exc[k];
            M = aff_mul(E, M);
        }

        // backbone coordinate
        {
            int o = kin_id[n];
            out[o * 3 + 0] = M.m[3];
            out[o * 3 + 1] = M.m[7];
            out[o * 3 + 2] = M.m[11];
        }
        // publish global transforms for side blocks (SoA, coalesced)
#pragma unroll
        for (int k = 0; k < 12; ++k) g_global[k * B_CHAIN + item] = M.m[k];
        __threadfence();
        __syncthreads();
        if (t == 0) atomicExch(&g_ready[bid], 1);

    } else {
        // ================= SIDE CHAINS =================
        // 8 lanes per chain; lane l<7 covers side positions {2l, 2l+1}, lane 7 covers {14}
        const int sb    = bid - NBB;
        const int chain = sb * CPS + (t >> 3);
        const int l     = t & 7;
        const int nb    = 1 + B_CHAIN + chain * S_SIDE;  // first side node id
        const int n0    = nb + 2 * l;
        const bool has2 = (l < 7);

        // ---- G-independent local work (overlaps the backbone phase) ----
        Aff H0 = build_ht_from(doftype[n0], dofs4[n0 - 1], n0, full_dofs);
        float t0x = H0.m[3], t0y = H0.m[7], t0z = H0.m[11];
        int o0 = kin_id[n0], o1 = 0;

        Aff S = H0;
        float tSx = 0.f, tSy = 0.f, tSz = 0.f;
        if (has2) {
            int n1 = n0 + 1;
            Aff H1 = build_ht_from(doftype[n1], dofs4[n1 - 1], n1, full_dofs);
            S = aff_mul(H0, H1);
            tSx = S.m[3]; tSy = S.m[7]; tSz = S.m[11];
            o1 = kin_id[n1];
        }

        // width-8 inclusive scan of segment products
#pragma unroll
        for (int d = 1; d < 8; d <<= 1) {
            Aff P = shfl_up_aff(S, d, 8);
            if (l >= d) S = aff_mul(P, S);
        }
        // exclusive shift
        Aff E = shfl_up_aff(S, 1, 8);
        if (l == 0) E = aff_identity();

        // ---- wait for this chunk's backbone transforms ----
        const int chunk = chain >> 9;  // 512 chains per backbone block
        {
            volatile int* vr = (volatile int*)g_ready;
            while (vr[chunk] == 0) { __nanosleep(64); }
            __threadfence();
        }
        Aff G;
#pragma unroll
        for (int k = 0; k < 12; ++k) G.m[k] = __ldcg(&g_global[k * B_CHAIN + chain]);

        Aff P = aff_mul(G, E);

        // node n0: coord = R(P)*t(H0) + t(P)
        {
            float cx = P.m[0]*t0x + P.m[1]*t0y + P.m[2]*t0z  + P.m[3];
            float cy = P.m[4]*t0x + P.m[5]*t0y + P.m[6]*t0z  + P.m[7];
            float cz = P.m[8]*t0x + P.m[9]*t0y + P.m[10]*t0z + P.m[11];
            out[o0 * 3 + 0] = cx;
            out[o0 * 3 + 1] = cy;
            out[o0 * 3 + 2] = cz;
        }
        if (has2) {
            float cx = P.m[0]*tSx + P.m[1]*tSy + P.m[2]*tSz  + P.m[3];
            float cy = P.m[4]*tSx + P.m[5]*tSy + P.m[6]*tSz  + P.m[7];
            float cz = P.m[8]*tSx + P.m[9]*tSy + P.m[10]*tSz + P.m[11];
            out[o1 * 3 + 0] = cx;
            out[o1 * 3 + 1] = cy;
            out[o1 * 3 + 2] = cz;
        }
    }

    // ---- reset scratch for the next graph replay (last block to finish) ----
    __syncthreads();
    if (t == 0) {
        int c = atomicAdd(&g_done, 1);
        if (c == NGRID - 1) {
#pragma unroll
            for (int i = 0; i < NBB; ++i) { g_flag[i] = 0; g_ready[i] = 0; }
            g_done = 0;
        }
    }
}

// ---------------- launch -----------------------------------------------------
extern "C" void kernel_launch(void* const* d_in, const int* in_sizes, int n_in,
                              void* d_out, int out_size) {
    // metadata order: dofs, full_dofs, node_idx, dof_idx, doftype,
    //                 gen0_nodes, gen1_nodes, gen1_parents, kin_id
    const float4* dofs4     = (const float4*)d_in[0];
    const float*  full_dofs = (const float*)d_in[1];
    const int*    doftype   = (const int*)d_in[4];
    const int*    kin_id    = (const int*)d_in[8];
    float* out = (float*)d_out;

    k_all<<<NGRID, TPB>>>(dofs4, full_dofs, doftype, kin_id, out);
}

// round 11
// speedup vs baseline: 1.2166x; 1.2166x over previous
#include <cuda_runtime.h>

#define B_CHAIN 16384
#define S_SIDE 15
#define NATM (1 + B_CHAIN + B_CHAIN * S_SIDE)   // 262145

#define NBB 32            // backbone scan blocks
#define TPB 512           // threads per backbone block (NBB*TPB == B_CHAIN)
#define NWARP (TPB / 32)  // 16

// Scratch (device globals; no runtime allocation allowed)
__device__ float g_H[12 * NATM];          // per-node transforms (SoA planes)
__device__ float g_loc[12 * B_CHAIN];     // block-local backbone scans (SoA)
__device__ float g_agg[NBB * 12];         // backbone block aggregates (AoS)

struct Aff { float m[12]; };  // row-major 3x4 affine; m[r*4+3] = translation

__device__ __forceinline__ Aff aff_identity() {
    Aff I;
#pragma unroll
    for (int k = 0; k < 12; ++k) I.m[k] = 0.0f;
    I.m[0] = I.m[5] = I.m[10] = 1.0f;
    return I;
}

__device__ __forceinline__ Aff aff_mul(const Aff& A, const Aff& B) {
    Aff C;
#pragma unroll
    for (int r = 0; r < 3; ++r) {
#pragma unroll
        for (int c = 0; c < 4; ++c) {
            float s = A.m[r*4+0] * B.m[0*4+c]
                    + A.m[r*4+1] * B.m[1*4+c]
                    + A.m[r*4+2] * B.m[2*4+c];
            if (c == 3) s += A.m[r*4+3];
            C.m[r*4+c] = s;
        }
    }
    return C;
}

__device__ __forceinline__ Aff shfl_up_aff(const Aff& a, int delta, int width) {
    Aff r;
#pragma unroll
    for (int k = 0; k < 12; ++k)
        r.m[k] = __shfl_up_sync(0xffffffffu, a.m[k], delta, width);
    return r;
}

__device__ __forceinline__ Aff shfl_down_aff(const Aff& a, int delta) {
    Aff r;
#pragma unroll
    for (int k = 0; k < 12; ++k)
        r.m[k] = __shfl_down_sync(0xffffffffu, a.m[k], delta, 32);
    return r;
}

// Per-node transform, closed forms, precise sincosf (error budget: backbone
// products over 16384 terms; rel_err ~1.03e-4 measured).
// doftype==2 (bond): Rx(d0) Rz(d1) T(d2,0,0) Rx(d3)
// doftype==1 (jump): T(d0,d1,d2) Rz(d5) Ry(d4) Rx(d3)
// doftype==0: identity
__device__ __forceinline__ Aff build_ht_from(int dt, float4 d, int n,
                                             const float* __restrict__ full_dofs) {
    if (dt == 0) return aff_identity();
    Aff H;
    if (dt == 2) {
        float sa, ca, sb, cb, sc, cc;
        sincosf(d.x, &sa, &ca);
        sincosf(d.y, &sb, &cb);
        sincosf(d.w, &sc, &cc);
        float x = d.z;
        H.m[0] = cb;      H.m[1]  = -sb * cc;             H.m[2]  = sb * sc;               H.m[3]  = cb * x;
        H.m[4] = ca * sb; H.m[5]  = ca * cb * cc - sa*sc; H.m[6]  = -ca * cb * sc - sa*cc; H.m[7]  = ca * sb * x;
        H.m[8] = sa * sb; H.m[9]  = sa * cb * cc + ca*sc; H.m[10] = -sa * cb * sc + ca*cc; H.m[11] = sa * sb * x;
    } else {
        float a = d.w;
        float b = full_dofs[n * 9 + 4];
        float g = full_dofs[n * 9 + 5];
        float sa, ca, sb, cb, sg, cg;
        sincosf(a, &sa, &ca);
        sincosf(b, &sb, &cb);
        sincosf(g, &sg, &cg);
        H.m[0] = cg * cb; H.m[1]  = cg * sb * sa - sg * ca; H.m[2]  = cg * sb * ca + sg * sa; H.m[3]  = d.x;
        H.m[4] = sg * cb; H.m[5]  = sg * sb * sa + cg * ca; H.m[6]  = sg * sb * ca - cg * sa; H.m[7]  = d.y;
        H.m[8] = -sb;     H.m[9]  = cb * sa;                H.m[10] = cb * ca;                H.m[11] = d.z;
    }
    return H;
}

// ============ K1: build ALL node transforms at full occupancy ================
__global__ void __launch_bounds__(256)
k1_build(const float4* __restrict__ dofs4,
         const float* __restrict__ full_dofs,
         const int* __restrict__ doftype) {
    int n = blockIdx.x * 256 + threadIdx.x + 1;   // node 1..NATM-1
    if (n >= NATM) return;
    Aff H = build_ht_from(doftype[n], dofs4[n - 1], n, full_dofs);
#pragma unroll
    for (int k = 0; k < 12; ++k) g_H[k * NATM + n] = H.m[k];
}

// ============ K2: backbone block-local scans (reads g_H, no sincos) ==========
__global__ void __launch_bounds__(TPB)
k2_scan() {
    const int t    = threadIdx.x;
    const int bid  = blockIdx.x;
    const int item = bid * TPB + t;
    const int n    = item + 1;        // backbone node 1..16384
    const int lane = t & 31;
    const int warp = t >> 5;

    __shared__ float s_agg[NWARP][12];
    __shared__ float s_inc[NWARP][12];

    Aff M;
#pragma unroll
    for (int k = 0; k < 12; ++k) M.m[k] = g_H[k * NATM + n];

    // warp shuffle inclusive scan
#pragma unroll
    for (int d = 1; d < 32; d <<= 1) {
        Aff P = shfl_up_aff(M, d, 32);
        if (lane >= d) M = aff_mul(P, M);
    }
    if (lane == 31) {
#pragma unroll
        for (int k = 0; k < 12; ++k) s_agg[warp][k] = M.m[k];
    }
    __syncthreads();

    if (warp == 0) {
        Aff A = aff_identity();
        if (lane < NWARP) {
#pragma unroll
            for (int k = 0; k < 12; ++k) A.m[k] = s_agg[lane][k];
        }
#pragma unroll
        for (int d = 1; d < NWARP; d <<= 1) {
            Aff P = shfl_up_aff(A, d, NWARP);
            if (lane >= d && lane < NWARP) A = aff_mul(P, A);
        }
        if (lane < NWARP) {
#pragma unroll
            for (int k = 0; k < 12; ++k) s_inc[lane][k] = A.m[k];
        }
        if (lane == NWARP - 1) {
#pragma unroll
            for (int k = 0; k < 12; ++k) g_agg[bid * 12 + k] = A.m[k];
        }
    }
    __syncthreads();

    if (warp > 0) {
        Aff W;
#pragma unroll
        for (int k = 0; k < 12; ++k) W.m[k] = s_inc[warp - 1][k];
        M = aff_mul(W, M);
    }
    // block-local inclusive scan value (SoA, coalesced)
#pragma unroll
    for (int k = 0; k < 12; ++k) g_loc[k * B_CHAIN + item] = M.m[k];
}

// ============ K3: apply prefixes + side chains + scatter ======================
// 256 threads/block = 32 chains x 8 lanes. 512 blocks. All 32 chains of a
// block share one backbone chunk (512 chains per K2 block, 16 blocks/chunk).
__global__ void __launch_bounds__(256)
k3_apply(const int* __restrict__ kin_id,
         float* __restrict__ out) {
    const int t     = threadIdx.x;
    const int bid   = blockIdx.x;
    const int chain = bid * 32 + (t >> 3);   // 0..B_CHAIN-1
    const int l     = t & 7;                 // lane within chain
    const int chunk = bid >> 4;              // backbone block id (0..31)

    __shared__ float s_pre[12];              // exclusive prefix of this chunk

    // warp 0 computes E = agg[0] * ... * agg[chunk-1] (ordered reduce)
    if (t < 32) {
        Aff V = aff_identity();
        if (t < chunk) {
#pragma unroll
            for (int k = 0; k < 12; ++k) V.m[k] = g_agg[t * 12 + k];
        }
#pragma unroll
        for (int d = 1; d < 32; d <<= 1) {
            Aff Hh = shfl_down_aff(V, d);
            if ((t & (2 * d - 1)) == 0) V = aff_mul(V, Hh);
        }
        if (t == 0) {
#pragma unroll
            for (int k = 0; k < 12; ++k) s_pre[k] = V.m[k];
        }
    }
    __syncthreads();

    // G = global transform of backbone node chain+1
    Aff G;
    {
        Aff E, L;
#pragma unroll
        for (int k = 0; k < 12; ++k) E.m[k] = s_pre[k];
#pragma unroll
        for (int k = 0; k < 12; ++k) L.m[k] = g_loc[k * B_CHAIN + chain];
        G = aff_mul(E, L);
    }

    // lane 0 writes the backbone coordinate
    if (l == 0) {
        int o = kin_id[chain + 1];
        out[o * 3 + 0] = G.m[3];
        out[o * 3 + 1] = G.m[7];
        out[o * 3 + 2] = G.m[11];
    }

    // side chain: lane l<7 covers side positions {2l, 2l+1}; lane 7 covers {14}
    const int nb   = 1 + B_CHAIN + chain * S_SIDE;
    const int n0   = nb + 2 * l;
    const bool has2 = (l < 7);

    Aff S;
#pragma unroll
    for (int k = 0; k < 12; ++k) S.m[k] = g_H[k * NATM + n0];
    float t0x = S.m[3], t0y = S.m[7], t0z = S.m[11];

    if (has2) {
        Aff H1;
#pragma unroll
        for (int k = 0; k < 12; ++k) H1.m[k] = g_H[k * NATM + n0 + 1];
        S = aff_mul(S, H1);
    }

    // width-8 inclusive scan of segment products
#pragma unroll
    for (int d = 1; d < 8; d <<= 1) {
        Aff P = shfl_up_aff(S, d, 8);
        if (l >= d) S = aff_mul(P, S);
    }
    // last node of this lane's segment: coord = R(G)*t(S_inc) + t(G)
    {
        int nlast = has2 ? (n0 + 1) : n0;
        int o = kin_id[nlast];
        float cx = G.m[0]*S.m[3] + G.m[1]*S.m[7] + G.m[2]*S.m[11]  + G.m[3];
        float cy = G.m[4]*S.m[3] + G.m[5]*S.m[7] + G.m[6]*S.m[11]  + G.m[7];
        float cz = G.m[8]*S.m[3] + G.m[9]*S.m[7] + G.m[10]*S.m[11] + G.m[11];
        out[o * 3 + 0] = cx;
        out[o * 3 + 1] = cy;
        out[o * 3 + 2] = cz;
    }
    // first node (only when the segment has two): coord = (G*E_side) applied to t(H0)
    if (has2) {
        Aff E = shfl_up_aff(S, 1, 8);
        if (l == 0) E = aff_identity();
        Aff P = aff_mul(G, E);
        int o = kin_id[n0];
        float cx = P.m[0]*t0x + P.m[1]*t0y + P.m[2]*t0z  + P.m[3];
        float cy = P.m[4]*t0x + P.m[5]*t0y + P.m[6]*t0z  + P.m[7];
        float cz = P.m[8]*t0x + P.m[9]*t0y + P.m[10]*t0z + P.m[11];
        out[o * 3 + 0] = cx;
        out[o * 3 + 1] = cy;
        out[o * 3 + 2] = cz;
    }
}

// ---------------- launch -----------------------------------------------------
extern "C" void kernel_launch(void* const* d_in, const int* in_sizes, int n_in,
                              void* d_out, int out_size) {
    // metadata order: dofs, full_dofs, node_idx, dof_idx, doftype,
    //                 gen0_nodes, gen1_nodes, gen1_parents, kin_id
    const float4* dofs4     = (const float4*)d_in[0];
    const float*  full_dofs = (const float*)d_in[1];
    const int*    doftype   = (const int*)d_in[4];
    const int*    kin_id    = (const int*)d_in[8];
    float* out = (float*)d_out;

    k1_build<<<(NATM - 1 + 255) / 256, 256>>>(dofs4, full_dofs, doftype);
    k2_scan<<<NBB, TPB>>>();
    k3_apply<<<B_CHAIN / 32, 256>>>(kin_id, out);
}